// round 1
// baseline (speedup 1.0000x reference)
#include <cuda_runtime.h>

// Problem constants (fixed shapes per reference)
#define IN_DIM   8192
#define HID_DIM  8192
#define COL4     (IN_DIM / 4)      // 2048 float4 per row
#define ROW_CHUNKS 64
#define ROWS_PER_CHUNK (HID_DIM / ROW_CHUNKS)  // 128

// Device-global scratch (allocation-free rule: device globals are allowed)
__device__ float g_partial[ROW_CHUNKS * IN_DIM];  // 2 MB
__device__ float g_wsum[IN_DIM];                  // 32 KB

// Kernel 1: partial column sums of W [HID, IN] row-major.
// grid = (COL4/256, ROW_CHUNKS), block = 256.
// Each thread owns 4 consecutive columns (one float4 lane), sums 128 rows.
__global__ __launch_bounds__(256) void colsum_partial(const float* __restrict__ w) {
    const int col4 = blockIdx.x * 256 + threadIdx.x;        // 0..2047
    const int r0   = blockIdx.y * ROWS_PER_CHUNK;
    const float4* __restrict__ w4 = reinterpret_cast<const float4*>(w);

    float4 acc = make_float4(0.f, 0.f, 0.f, 0.f);
    #pragma unroll 8
    for (int r = 0; r < ROWS_PER_CHUNK; ++r) {
        float4 v = __ldg(&w4[(size_t)(r0 + r) * COL4 + col4]);
        acc.x += v.x; acc.y += v.y; acc.z += v.z; acc.w += v.w;
    }
    reinterpret_cast<float4*>(g_partial)[(size_t)blockIdx.y * COL4 + col4] = acc;
}

// Kernel 2: reduce the 64 partials into g_wsum. grid = (COL4/256), block = 256.
__global__ __launch_bounds__(256) void reduce_partial() {
    const int col4 = blockIdx.x * 256 + threadIdx.x;
    const float4* __restrict__ p4 = reinterpret_cast<const float4*>(g_partial);
    float4 acc = make_float4(0.f, 0.f, 0.f, 0.f);
    #pragma unroll
    for (int c = 0; c < ROW_CHUNKS; ++c) {
        float4 v = p4[(size_t)c * COL4 + col4];
        acc.x += v.x; acc.y += v.y; acc.z += v.z; acc.w += v.w;
    }
    reinterpret_cast<float4*>(g_wsum)[col4] = acc;
}

// Kernel 3: out[b] = 0.75 * dot(x[b], g_wsum). One block per batch row.
__global__ __launch_bounds__(256) void rowdot(const float* __restrict__ x,
                                              float* __restrict__ out) {
    const int b = blockIdx.x;
    const float4* __restrict__ x4 =
        reinterpret_cast<const float4*>(x + (size_t)b * IN_DIM);
    const float4* __restrict__ w4 = reinterpret_cast<const float4*>(g_wsum);

    float acc = 0.f;
    // 2048 float4 / 256 threads = 8 per thread (unrolled, MLP=8)
    #pragma unroll
    for (int k = 0; k < COL4 / 256; ++k) {
        const int i = threadIdx.x + k * 256;
        float4 xv = __ldg(&x4[i]);
        float4 wv = w4[i];
        acc = fmaf(xv.x, wv.x, acc);
        acc = fmaf(xv.y, wv.y, acc);
        acc = fmaf(xv.z, wv.z, acc);
        acc = fmaf(xv.w, wv.w, acc);
    }

    // warp reduce
    #pragma unroll
    for (int off = 16; off > 0; off >>= 1)
        acc += __shfl_xor_sync(0xFFFFFFFFu, acc, off);

    __shared__ float warp_sums[8];
    const int lane = threadIdx.x & 31;
    const int wid  = threadIdx.x >> 5;
    if (lane == 0) warp_sums[wid] = acc;
    __syncthreads();

    if (wid == 0) {
        float v = (lane < 8) ? warp_sums[lane] : 0.f;
        #pragma unroll
        for (int off = 4; off > 0; off >>= 1)
            v += __shfl_xor_sync(0xFFFFFFFFu, v, off);
        if (lane == 0) out[b] = v * 0.75f;   // (/2) * 1.5
    }
}

extern "C" void kernel_launch(void* const* d_in, const int* in_sizes, int n_in,
                              void* d_out, int out_size) {
    const float* x = (const float*)d_in[0];      // [B, IN]
    const float* w = (const float*)d_in[1];      // [HID, IN]
    float* out = (float*)d_out;                  // [B, 1]
    const int B = in_sizes[0] / IN_DIM;

    dim3 g1(COL4 / 256, ROW_CHUNKS);
    colsum_partial<<<g1, 256>>>(w);
    reduce_partial<<<COL4 / 256, 256>>>();
    rowdot<<<B, 256>>>(x, out);
}